// round 15
// baseline (speedup 1.0000x reference)
#include <cuda_runtime.h>
#include <cuda_bf16.h>
#include <math.h>
#include <stdint.h>

#define BATCH 8
#define SEQ   1024
#define DMODEL 768
#define NHEAD 12
#define NKV   4
#define NREP  3
#define HD    64
#define MROWS (BATCH*SEQ)   // 8192
#define KDIM  768
#define NQKV  1280          // 768 + 256 + 256

#if defined(__CUDA_ARCH__) && (defined(__CUDA_ARCH_FEAT_SM103_ALL) || defined(__CUDA_ARCH_FEAT_SM100_ALL) || defined(__CUDA_ARCH_SPECIFIC__))
#define GQA_TCGEN05 1
#else
#define GQA_TCGEN05 0
#endif

// ---------------- scratch ----------------
__device__ __align__(256) float g_Vp[MROWS * 256];
__device__ __align__(256) __nv_bfloat16 g_Xhi[MROWS * KDIM];
__device__ __align__(256) __nv_bfloat16 g_Xlo[MROWS * KDIM];
__device__ __align__(256) __nv_bfloat16 g_AOhi[MROWS * KDIM];
__device__ __align__(256) __nv_bfloat16 g_AOlo[MROWS * KDIM];
__device__ __align__(256) __nv_bfloat16 g_Qhb[BATCH * NHEAD * SEQ * HD];
__device__ __align__(256) __nv_bfloat16 g_Qlb[BATCH * NHEAD * SEQ * HD];
__device__ __align__(256) __nv_bfloat16 g_Khb[BATCH * NKV * SEQ * HD];
__device__ __align__(256) __nv_bfloat16 g_Klb[BATCH * NKV * SEQ * HD];
__device__ __align__(256) __nv_bfloat16 g_Vthb[BATCH * NKV * HD * SEQ];
__device__ __align__(256) __nv_bfloat16 g_Vtlb[BATCH * NKV * HD * SEQ];
__device__ __align__(256) float g_cost[SEQ * 32];
__device__ __align__(256) float g_sint[SEQ * 32];
#define WQ_OFF 0
#define WK_OFF (768*768)
#define WV_OFF (WK_OFF + 256*768)
#define WO_OFF (WV_OFF + 256*768)
#define WT_TOT (WO_OFF + 768*768)
__device__ __align__(256) __nv_bfloat16 g_Whi[WT_TOT];
__device__ __align__(256) __nv_bfloat16 g_Wlo[WT_TOT];

// ---------------- ptx helpers ----------------
__device__ __forceinline__ uint32_t smem_u32(const void* p) {
    uint32_t a;
    asm("{ .reg .u64 t; cvta.to.shared.u64 t, %1; cvt.u32.u64 %0, t; }" : "=r"(a) : "l"(p));
    return a;
}
#if GQA_TCGEN05
__device__ __forceinline__ uint32_t elect_one() {
    uint32_t p;
    asm volatile("{\n\t.reg .pred p;\n\telect.sync _|p, 0xFFFFFFFF;\n\tselp.b32 %0, 1, 0, p;\n\t}" : "=r"(p));
    return p;
}
__device__ __forceinline__ void mma_f16_ss(uint32_t d, uint64_t ad, uint64_t bd,
                                           uint32_t idesc, uint32_t acc) {
    asm volatile(
        "{\n\t.reg .pred p;\n\tsetp.ne.u32 p, %5, 0;\n\t"
        "tcgen05.mma.cta_group::1.kind::f16 [%0], %1, %2, %3, {%4, %4, %4, %4}, p;\n\t}"
        :: "r"(d), "l"(ad), "l"(bd), "r"(idesc), "r"(0u), "r"(acc) : "memory");
}
__device__ __forceinline__ void mma_f16_ts(uint32_t d, uint32_t a_tmem, uint64_t bd,
                                           uint32_t idesc, uint32_t acc) {
    asm volatile(
        "{\n\t.reg .pred p;\n\tsetp.ne.u32 p, %5, 0;\n\t"
        "tcgen05.mma.cta_group::1.kind::f16 [%0], [%1], %2, %3, {%4, %4, %4, %4}, p;\n\t}"
        :: "r"(d), "r"(a_tmem), "l"(bd), "r"(idesc), "r"(0u), "r"(acc) : "memory");
}
__device__ __forceinline__ void cp16(uint32_t dst, const void* src) {
    asm volatile("cp.async.cg.shared.global [%0], [%1], 16;" :: "r"(dst), "l"(src) : "memory");
}
#define CP_COMMIT() asm volatile("cp.async.commit_group;" ::: "memory")
#define CP_WAIT(n)  asm volatile("cp.async.wait_group %0;" :: "n"(n) : "memory")
#define TC_ALLOC(sm, n)   asm volatile("tcgen05.alloc.cta_group::1.sync.aligned.shared::cta.b32 [%0], %1;" :: "r"(sm), "r"(n) : "memory")
#define TC_RELINQ()       asm volatile("tcgen05.relinquish_alloc_permit.cta_group::1.sync.aligned;")
#define TC_DEALLOC(t, n)  asm volatile("tcgen05.dealloc.cta_group::1.sync.aligned.b32 %0, %1;" :: "r"(t), "r"(n))
#define TC_COMMIT(mb)     asm volatile("tcgen05.commit.cta_group::1.mbarrier::arrive::one.shared::cluster.b64 [%0];" :: "r"(mb) : "memory")
#define TC_WAIT_LD()      asm volatile("tcgen05.wait::ld.sync.aligned;" ::: "memory")
#define TC_WAIT_ST()      asm volatile("tcgen05.wait::st.sync.aligned;" ::: "memory")
#define TC_FENCE_AFTER()  asm volatile("tcgen05.fence::after_thread_sync;" ::: "memory")
#define TC_FENCE_BEFORE() asm volatile("tcgen05.fence::before_thread_sync;" ::: "memory")
#define MBAR_INIT(mb, c)  asm volatile("mbarrier.init.shared.b64 [%0], %1;" :: "r"(mb), "r"(c) : "memory")
#define MBAR_INVAL(mb)    asm volatile("mbarrier.inval.shared.b64 [%0];" :: "r"(mb) : "memory")
#define FENCE_ASYNC()     asm volatile("fence.proxy.async.shared::cta;" ::: "memory")

__device__ __forceinline__ void mbar_wait(uint32_t mb, uint32_t parity) {
    asm volatile(
        "{\n\t.reg .pred P1;\n\t"
        "WAIT_LOOP_%=:\n\t"
        "mbarrier.try_wait.parity.acquire.cta.shared::cta.b64 P1, [%0], %1, 0x989680;\n\t"
        "@P1 bra.uni WAIT_DONE_%=;\n\t"
        "bra.uni WAIT_LOOP_%=;\n\t"
        "WAIT_DONE_%=:\n\t}"
        :: "r"(mb), "r"(parity) : "memory");
}
#define LDTM_X32(r, addr) \
    asm volatile("tcgen05.ld.sync.aligned.32x32b.x32.b32 " \
        "{%0,%1,%2,%3,%4,%5,%6,%7,%8,%9,%10,%11,%12,%13,%14,%15," \
        "%16,%17,%18,%19,%20,%21,%22,%23,%24,%25,%26,%27,%28,%29,%30,%31}, [%32];" \
        : "=r"((r)[0]),"=r"((r)[1]),"=r"((r)[2]),"=r"((r)[3]),"=r"((r)[4]),"=r"((r)[5]),"=r"((r)[6]),"=r"((r)[7]), \
          "=r"((r)[8]),"=r"((r)[9]),"=r"((r)[10]),"=r"((r)[11]),"=r"((r)[12]),"=r"((r)[13]),"=r"((r)[14]),"=r"((r)[15]), \
          "=r"((r)[16]),"=r"((r)[17]),"=r"((r)[18]),"=r"((r)[19]),"=r"((r)[20]),"=r"((r)[21]),"=r"((r)[22]),"=r"((r)[23]), \
          "=r"((r)[24]),"=r"((r)[25]),"=r"((r)[26]),"=r"((r)[27]),"=r"((r)[28]),"=r"((r)[29]),"=r"((r)[30]),"=r"((r)[31]) \
        : "r"(addr))
#define STTM_X16(addr, r) \
    asm volatile("tcgen05.st.sync.aligned.32x32b.x16.b32 [%0], " \
        "{%1,%2,%3,%4,%5,%6,%7,%8,%9,%10,%11,%12,%13,%14,%15,%16};" \
        :: "r"(addr), \
           "r"((r)[0]),"r"((r)[1]),"r"((r)[2]),"r"((r)[3]),"r"((r)[4]),"r"((r)[5]),"r"((r)[6]),"r"((r)[7]), \
           "r"((r)[8]),"r"((r)[9]),"r"((r)[10]),"r"((r)[11]),"r"((r)[12]),"r"((r)[13]),"r"((r)[14]),"r"((r)[15]) \
        : "memory")
#endif // GQA_TCGEN05

__device__ __forceinline__ uint32_t sw128(uint32_t b) { return b ^ ((b >> 3) & 0x70); }
__device__ __forceinline__ uint64_t make_desc(uint32_t addr) {
    const uint64_t base = (uint64_t(2) << 61) | (uint64_t(1) << 46) |
                          (uint64_t(64) << 32) | (uint64_t(1) << 16);
    return base | ((uint64_t)(addr >> 4) & 0x3FFF);
}
__device__ __forceinline__ uint32_t pack_bf2(__nv_bfloat16 a, __nv_bfloat16 b) {
    __nv_bfloat162 t; t.x = a; t.y = b;
    return *(uint32_t*)&t;
}

// ---------------- merged weight prep ----------------
__global__ void wsplit_all_kernel(const float* __restrict__ qw, const float* __restrict__ kw,
                                  const float* __restrict__ vw, const float* __restrict__ ow)
{
    __shared__ float t[32][33];
    const int tx = threadIdx.x, ty = threadIdx.y;
    const int k0 = blockIdx.x * 32;
    const int nt = blockIdx.y;
    const float* W; int N, off, n0;
    if (nt < 24)      { W = qw; N = 768; off = WQ_OFF; n0 = nt * 32; }
    else if (nt < 32) { W = kw; N = 256; off = WK_OFF; n0 = (nt - 24) * 32; }
    else if (nt < 40) { W = vw; N = 256; off = WV_OFF; n0 = (nt - 32) * 32; }
    else              { W = ow; N = 768; off = WO_OFF; n0 = (nt - 40) * 32; }
#pragma unroll
    for (int i = ty; i < 32; i += 8)
        t[i][tx] = W[(size_t)(k0 + i) * N + n0 + tx];
    __syncthreads();
#pragma unroll
    for (int i = ty; i < 32; i += 8) {
        float v = t[tx][i];
        __nv_bfloat16 h = __float2bfloat16(v);
        __nv_bfloat16 l = __float2bfloat16(v - __bfloat162float(h));
        g_Whi[off + (size_t)(n0 + i) * KDIM + k0 + tx] = h;
        g_Wlo[off + (size_t)(n0 + i) * KDIM + k0 + tx] = l;
    }
}

// ---------------- activation split ----------------
__global__ __launch_bounds__(256) void asplit_kernel(
    const float* __restrict__ in, __nv_bfloat16* __restrict__ hi,
    __nv_bfloat16* __restrict__ lo)
{
    const size_t i = (size_t)blockIdx.x * 256 + threadIdx.x;
    float4 v = ((const float4*)in)[i];
    __nv_bfloat16 h0 = __float2bfloat16(v.x), h1 = __float2bfloat16(v.y);
    __nv_bfloat16 h2 = __float2bfloat16(v.z), h3 = __float2bfloat16(v.w);
    __nv_bfloat16 l0 = __float2bfloat16(v.x - __bfloat162float(h0));
    __nv_bfloat16 l1 = __float2bfloat16(v.y - __bfloat162float(h1));
    __nv_bfloat16 l2 = __float2bfloat16(v.z - __bfloat162float(h2));
    __nv_bfloat16 l3 = __float2bfloat16(v.w - __bfloat162float(h3));
    ((uint2*)hi)[i] = make_uint2(pack_bf2(h0, h1), pack_bf2(h2, h3));
    ((uint2*)lo)[i] = make_uint2(pack_bf2(l0, l1), pack_bf2(l2, l3));
}

// ---------------- RoPE table ----------------
__global__ void ropetab_kernel(const int* __restrict__ pos)
{
    const int t = blockIdx.x, j = threadIdx.x;
    const float LOG2_10000_OVER_32 = 0.41524101186092f;
    float th = (float)pos[t] * exp2f(-(float)j * LOG2_10000_OVER_32);
    float s, c;
    sincosf(th, &s, &c);
    g_cost[t * 32 + j] = c;
    g_sint[t * 32 + j] = s;
}

// ---------------- V transpose + split ----------------
__global__ void vtsplit_kernel(const float* __restrict__ Vp,
                               __nv_bfloat16* __restrict__ Vth,
                               __nv_bfloat16* __restrict__ Vtl)
{
    __shared__ float t[32][33];
    const int tx = threadIdx.x, ty = threadIdx.y;
    const int t0 = blockIdx.x * 32, d0 = blockIdx.y * 32;
    const int b = blockIdx.z >> 2, g = blockIdx.z & 3;
#pragma unroll
    for (int i = ty; i < 32; i += 8)
        t[i][tx] = Vp[((size_t)b * SEQ + t0 + i) * 256 + g * HD + d0 + tx];
    __syncthreads();
#pragma unroll
    for (int i = ty; i < 32; i += 8) {
        float v = t[tx][i];
        __nv_bfloat16 h = __float2bfloat16(v);
        __nv_bfloat16 l = __float2bfloat16(v - __bfloat162float(h));
        const size_t o = (((size_t)b * NKV + g) * HD + d0 + i) * SEQ + t0 + tx;
        Vth[o] = h; Vtl[o] = l;
    }
}

// ---------------- tcgen05 GEMM: 128x256 tiles, 2-stage cp.async pipeline -----------
#define NCHUNK   (KDIM/64)        // 12
#define GSM_MB0  16
#define GSM_ATILE 16384           // 128 rows x 128B
#define GSM_BTILE 32768           // 256 rows x 128B
#define GSM_STAGE (2*GSM_ATILE + 2*GSM_BTILE)   // 98304 (AH, AL, BH, BL)
#define GSM_TOTAL (1024 + 2*GSM_STAGE)          // 197632

__global__ __launch_bounds__(256) void gemm_tc_kernel(
    const __nv_bfloat16* __restrict__ Ahi, const __nv_bfloat16* __restrict__ Alo,
    const __nv_bfloat16* __restrict__ Bhi, const __nv_bfloat16* __restrict__ Blo,
    const float* __restrict__ bq, const float* __restrict__ bk,
    const float* __restrict__ bv, float* __restrict__ C, int Ntot, int mode)
{
#if GQA_TCGEN05
    extern __shared__ char smem[];
    const uint32_t smb = smem_u32(smem);
    const int tid = threadIdx.x;
    const int wid = tid >> 5, lane = tid & 31;

    if (wid == 0) { TC_ALLOC(smb, 256); TC_RELINQ(); }
    if (tid == 0) {
        MBAR_INIT(smb + GSM_MB0, 1);
        MBAR_INIT(smb + GSM_MB0 + 8, 1);
    }
    __syncthreads();
    uint32_t tmem;
    asm volatile("ld.shared.b32 %0, [%1];" : "=r"(tmem) : "r"(smb));

    const int brow = blockIdx.y * 128;
    const int bcol = blockIdx.x * 256;
    const __nv_bfloat16* Ahp = Ahi + (size_t)brow * KDIM;
    const __nv_bfloat16* Alp = Alo + (size_t)brow * KDIM;
    const __nv_bfloat16* Bhp = Bhi + (size_t)bcol * KDIM;
    const __nv_bfloat16* Blp = Blo + (size_t)bcol * KDIM;

    // idesc: f32 acc, bf16 x bf16, N=256, M=128
    const uint32_t idesc = (1u << 4) | (1u << 7) | (1u << 10) |
                           ((256u / 8) << 17) | ((128u / 16) << 24);

    auto fill_chunk = [&](int ch, int st) {
        const uint32_t sa = smb + 1024 + (uint32_t)st * GSM_STAGE;
        const int kc0 = ch * 64;
        // A: 128 rows (hi+lo)
#pragma unroll
        for (int j = 0; j < 4; j++) {
            const int idx = j * 256 + tid;
            const int row = idx >> 3, c8 = (idx & 7) << 3;
            const uint32_t sw = sw128(row * 128 + c8 * 2);
            const size_t go = (size_t)row * KDIM + kc0 + c8;
            cp16(sa + sw,             Ahp + go);
            cp16(sa + GSM_ATILE + sw, Alp + go);
        }
        // B: 256 rows (hi+lo)
        const uint32_t bbase = sa + 2 * GSM_ATILE;
#pragma unroll
        for (int j = 0; j < 8; j++) {
            const int idx = j * 256 + tid;
            const int row = idx >> 3, c8 = (idx & 7) << 3;
            const uint32_t sw = sw128(row * 128 + c8 * 2);
            const size_t go = (size_t)row * KDIM + kc0 + c8;
            cp16(bbase + sw,             Bhp + go);
            cp16(bbase + GSM_BTILE + sw, Blp + go);
        }
    };

    fill_chunk(0, 0);
    CP_COMMIT();

    for (int ch = 0; ch < NCHUNK; ch++) {
        const int st = ch & 1;
        CP_WAIT(0);
        FENCE_ASYNC();
        __syncthreads();

        if (wid == 0) {
            if (elect_one()) {
                const uint32_t sa = smb + 1024 + (uint32_t)st * GSM_STAGE;
                const uint64_t dah = make_desc(sa);
                const uint64_t dal = make_desc(sa + GSM_ATILE);
                const uint64_t dbh = make_desc(sa + 2 * GSM_ATILE);
                const uint64_t dbl = make_desc(sa + 2 * GSM_ATILE + GSM_BTILE);
#pragma unroll
                for (int ks = 0; ks < 4; ks++) {
                    const uint64_t o = ks * 2;
                    mma_f16_ss(tmem, dah + o, dbh + o, idesc, (ch > 0 || ks > 0) ? 1u : 0u);
                    mma_f16_ss(tmem, dah + o, dbl + o, idesc, 1u);
                    mma_f16_ss(tmem, dal + o, dbh + o, idesc, 1u);
                }
                TC_COMMIT(smb + GSM_MB0 + (uint32_t)st * 8);
            }
        }

        const int nxt = ch + 1;
        if (nxt < NCHUNK) {
            // stage (ch+1)&1 last read by MMA(ch-1); wait overlaps MMA(ch)
            if (ch >= 1)
                mbar_wait(smb + GSM_MB0 + (uint32_t)((ch - 1) & 1) * 8,
                          (uint32_t)(((ch - 1) >> 1) & 1));
            fill_chunk(nxt, nxt & 1);
            CP_COMMIT();
        }
    }

    mbar_wait(smb + GSM_MB0 + (uint32_t)((NCHUNK - 1) & 1) * 8,
              (uint32_t)(((NCHUNK - 1) >> 1) & 1));
    TC_FENCE_AFTER();

    // epilogue: warp w -> rows (w&3)*32+lane, cols (w>>2)*128 .. +128 (two 64-col halves)
    const int m = brow + (wid & 3) * 32 + lane;
    const int b_ = m >> 10, t_ = m & (SEQ - 1);

    float ct[32], st2[32];
    if (mode == 1) {
        const float* cb = g_cost + t_ * 32;
        const float* sb = g_sint + t_ * 32;
#pragma unroll
        for (int u = 0; u < 8; u++) {
            *(float4*)&ct[u * 4] = *(const float4*)&cb[u * 4];
            *(float4*)&st2[u * 4] = *(const float4*)&sb[u * 4];
        }
    }

#pragma unroll
    for (int h64 = 0; h64 < 2; h64++) {
        const int ch2 = (wid >> 2) * 128 + h64 * 64;
        const int hcol = bcol + ch2;
        float val[64];
#pragma unroll
        for (int half = 0; half < 2; half++) {
            uint32_t r[32];
            LDTM_X32(r, tmem + ch2 + half * 32);
            TC_WAIT_LD();
#pragma unroll
            for (int i = 0; i < 32; i++) {
                const int cc = hcol + half * 32 + i;
                const float bb = (cc < 768) ? bq[cc] : ((cc < 1024) ? bk[cc - 768] : bv[cc - 1024]);
                val[half * 32 + i] = __uint_as_float(r[i]) + bb;
            }
        }

        if (mode == 0) {
#pragma unroll
            for (int u = 0; u < 16; u++)
                *(float4*)&C[(size_t)m * Ntot + hcol + u * 4] = *(float4*)&val[u * 4];
        } else {
            if (hcol >= 1024) {
                float* dst = g_Vp + (size_t)m * 256 + (hcol - 1024);
#pragma unroll
                for (int u = 0; u < 16; u++)
                    *(float4*)(dst + u * 4) = *(float4*)&val[u * 4];
            } else {
                __nv_bfloat16 *dh, *dl;
                if (hcol < 768) {
                    const int hh = hcol >> 6;
                    const size_t o = (((size_t)b_ * NHEAD + hh) * SEQ + t_) * HD;
                    dh = g_Qhb + o; dl = g_Qlb + o;
                } else {
                    const int gg = (hcol - 768) >> 6;
                    const size_t o = (((size_t)b_ * NKV + gg) * SEQ + t_) * HD;
                    dh = g_Khb + o; dl = g_Klb + o;
                }
                {
                    uint32_t hb[16], lb[16];
#pragma unroll
                    for (int u = 0; u < 16; u++) {
                        const int k0 = 2 * u, k1 = 2 * u + 1;
                        const float r0 = val[k0] * ct[k0] - val[16 + u] * st2[k0];
                        const float r1 = val[k1] * ct[k1] - val[48 + u] * st2[k1];
                        __nv_bfloat16 h0 = __float2bfloat16(r0), h1 = __float2bfloat16(r1);
                        hb[u] = pack_bf2(h0, h1);
                        lb[u] = pack_bf2(__float2bfloat16(r0 - __bfloat162float(h0)),
                                         __float2bfloat16(r1 - __bfloat162float(h1)));
                    }
#pragma unroll
                    for (int u = 0; u < 4; u++) {
                        *(uint4*)(dh + u * 8) = *(uint4*)&hb[u * 4];
                        *(uint4*)(dl + u * 8) = *(uint4*)&lb[u * 4];
                    }
                }
                {
                    uint32_t hb[16], lb[16];
#pragma unroll
                    for (int u = 0; u < 16; u++) {
                        const int j0 = 2 * u, j1 = 2 * u + 1;
                        const float r0 = val[32 + j0] * ct[j0] + val[u] * st2[j0];
                        const float r1 = val[32 + j1] * ct[j1] + val[32 + u] * st2[j1];
                        __nv_bfloat16 h0 = __float2bfloat16(r0), h1 = __float2bfloat16(r1);
                        hb[u] = pack_bf2(h0, h1);
                        lb[u] = pack_bf2(__float2bfloat16(r0 - __bfloat162float(h0)),
                                         __float2bfloat16(r1 - __bfloat162float(h1)));
                    }
#pragma unroll
                    for (int u = 0; u < 4; u++) {
                        *(uint4*)(dh + 32 + u * 8) = *(uint4*)&hb[u * 4];
                        *(uint4*)(dl + 32 + u * 8) = *(uint4*)&lb[u * 4];
                    }
                }
            }
        }
    }
    TC_FENCE_BEFORE();
    __syncthreads();
    if (tid == 0) {
        MBAR_INVAL(smb + GSM_MB0);
        MBAR_INVAL(smb + GSM_MB0 + 8);
    }
    if (wid == 0) TC_DEALLOC(tmem, 256);
#else
    // fallback (never selected at runtime when sm_103a cubin exists)
    const int brow = blockIdx.y * 128, bcol = blockIdx.x * 256;
    if ((int)threadIdx.x >= 128) return;
    const int row = brow + (int)threadIdx.x;
    const int b_ = row >> 10, t_ = row & (SEQ - 1);
    for (int hc = 0; hc < 4; hc++) {
        const int hcol = bcol + hc * 64;
        float v[64];
        for (int c = 0; c < 64; c++) {
            const int col = hcol + c;
            float a_ = 0.f;
            for (int k = 0; k < KDIM; k++) {
                float a = __bfloat162float(Ahi[(size_t)row * KDIM + k]) +
                          __bfloat162float(Alo[(size_t)row * KDIM + k]);
                float w = __bfloat162float(Bhi[(size_t)col * KDIM + k]) +
                          __bfloat162float(Blo[(size_t)col * KDIM + k]);
                a_ += a * w;
            }
            float bb = (col < 768) ? bq[col] : ((col < 1024) ? bk[col - 768] : bv[col - 1024]);
            v[c] = a_ + bb;
        }
        if (mode == 0) {
            for (int c = 0; c < 64; c++) C[(size_t)row * Ntot + hcol + c] = v[c];
        } else if (hcol >= 1024) {
            for (int c = 0; c < 64; c++) g_Vp[(size_t)row * 256 + (hcol - 1024) + c] = v[c];
        } else {
            __nv_bfloat16 *dh, *dl;
            if (hcol < 768) {
                const size_t o = (((size_t)b_ * NHEAD + (hcol >> 6)) * SEQ + t_) * HD;
                dh = g_Qhb + o; dl = g_Qlb + o;
            } else {
                const size_t o = (((size_t)b_ * NKV + ((hcol - 768) >> 6)) * SEQ + t_) * HD;
                dh = g_Khb + o; dl = g_Klb + o;
            }
            for (int k = 0; k < 64; k++) {
                const int j = k & 31;
                float ctv = g_cost[t_ * 32 + j], stv = g_sint[t_ * 32 + j];
                float res;
                if (k < 32) {
                    const int pidx = (k & 1) ? 48 + (k >> 1) : 16 + (k >> 1);
                    res = v[k] * ctv - v[pidx] * stv;
                } else {
                    const int pidx = (j & 1) ? 32 + (j >> 1) : (j >> 1);
                    res = v[k] * ctv + v[pidx] * stv;
                }
                __nv_bfloat16 h = __float2bfloat16(res);
                dh[k] = h;
                dl[k] = __float2bfloat16(res - __bfloat162float(h));
            }
        }
    }
#endif
}

// ---------------- tcgen05 flash attention (unchanged from R14) ---------------------
#define ATT_MBS  16
#define ATT_MBO0 24
#define ATT_MBO1 32
#define AQ1H 1024
#define AQ1L (AQ1H + 16384)
#define AQ2H (AQ1L + 16384)
#define AQ2L (AQ2H + 16384)
#define AKV0 (AQ2L + 16384)
#define ATT_TOTAL (AKV0 + 2*65536)   // 197632 bytes
#define TM_S1 0
#define TM_S2 128
#define TM_O1 256
#define TM_O2 320

__global__ __launch_bounds__(256) void attn_tc_kernel(
    const __nv_bfloat16* __restrict__ Qh, const __nv_bfloat16* __restrict__ Ql,
    const __nv_bfloat16* __restrict__ Kh, const __nv_bfloat16* __restrict__ Kl,
    const __nv_bfloat16* __restrict__ Vth, const __nv_bfloat16* __restrict__ Vtl)
{
    const int p = blockIdx.x, h = blockIdx.y, b = blockIdx.z;
    const int g = h / NREP;
    const int qlo = p, qhi = (SEQ / 128 - 1) - p;
#if GQA_TCGEN05
    extern __shared__ char smem[];
    const uint32_t smb = smem_u32(smem);
    const int tid = threadIdx.x;
    const int wid = tid >> 5, lane = tid & 31;

    if (wid == 0) { TC_ALLOC(smb, 512); TC_RELINQ(); }
    if (tid == 0) {
        MBAR_INIT(smb + ATT_MBS, 1);
        MBAR_INIT(smb + ATT_MBO0, 1);
        MBAR_INIT(smb + ATT_MBO1, 1);
    }
    __syncthreads();
    uint32_t tmem;
    asm volatile("ld.shared.b32 %0, [%1];" : "=r"(tmem) : "r"(smb));

    {
        const __nv_bfloat16* q1h = Qh + (((size_t)b * NHEAD + h) * SEQ + qlo * 128) * HD;
        const __nv_bfloat16* q1l = Ql + (((size_t)b * NHEAD + h) * SEQ + qlo * 128) * HD;
        const __nv_bfloat16* q2h = Qh + (((size_t)b * NHEAD + h) * SEQ + qhi * 128) * HD;
        const __nv_bfloat16* q2l = Ql + (((size_t)b * NHEAD + h) * SEQ + qhi * 128) * HD;
#pragma unroll
        for (int j = 0; j < 4; j++) {
            const int idx = j * 256 + tid;
            const int row = idx >> 3, c8 = (idx & 7) << 3;
            const uint32_t sw = sw128(row * 128 + c8 * 2);
            const size_t go = (size_t)row * HD + c8;
            cp16(smb + AQ1H + sw, q1h + go);
            cp16(smb + AQ1L + sw, q1l + go);
            cp16(smb + AQ2H + sw, q2h + go);
            cp16(smb + AQ2L + sw, q2l + go);
        }
        CP_COMMIT();
    }

    const int r = (wid & 3) * 32 + lane;
    const int cbase = (wid >> 2) * 64;
    const uint32_t warpofs = (uint32_t)(wid & 3) << 21;
    float lacc1 = 0.f, lacc2 = 0.f;

    const uint32_t idescS = (1u << 4) | (1u << 7) | (1u << 10) | (16u << 17) | (8u << 24);
    const uint32_t idescO = (1u << 4) | (1u << 7) | (1u << 10) | (8u << 17)  | (8u << 24);

    const __nv_bfloat16* Khp = Kh + ((size_t)b * NKV + g) * SEQ * HD;
    const __nv_bfloat16* Klp = Kl + ((size_t)b * NKV + g) * SEQ * HD;
    const __nv_bfloat16* Vhp = Vth + ((size_t)b * NKV + g) * HD * SEQ;
    const __nv_bfloat16* Vlp = Vtl + ((size_t)b * NKV + g) * HD * SEQ;

    const int nkt = qhi + 1;
    for (int kt = 0; kt < nkt; kt++) {
        const bool act1 = (kt <= qlo);
        const int sb = kt & 1;
        const uint32_t mbo = smb + (sb ? ATT_MBO1 : ATT_MBO0);
        if (kt >= 2) mbar_wait(mbo, (uint32_t)(((kt - 2) >> 1) & 1));

        const uint32_t KH = AKV0 + sb * 65536;
        const uint32_t KL = KH + 16384, VH = KH + 32768, VL = KH + 49152;

#pragma unroll
        for (int j = 0; j < 4; j++) {
            const int idx = j * 256 + tid;
            const int row = idx >> 3, c8 = (idx & 7) << 3;
            const uint32_t sw = sw128(row * 128 + c8 * 2);
            const size_t go = (size_t)(kt * 128 + row) * HD + c8;
            cp16(smb + KH + sw, Khp + go);
            cp16(smb + KL + sw, Klp + go);
            const int d = idx >> 4, vch = idx & 15;
            const int key0 = vch * 8;
            const uint32_t voff = ((key0 & 64) ? 8192u : 0u) + d * 128 + (key0 & 63) * 2;
            const uint32_t vsw = sw128(voff);
            const size_t vgo = (size_t)d * SEQ + kt * 128 + key0;
            cp16(smb + VH + vsw, Vhp + vgo);
            cp16(smb + VL + vsw, Vlp + vgo);
        }
        CP_COMMIT();
        CP_WAIT(0);
        FENCE_ASYNC();
        __syncthreads();

        if (wid == 0) {
            if (elect_one()) {
                const uint64_t dkh = make_desc(smb + KH);
                const uint64_t dkl = make_desc(smb + KL);
                const uint64_t dq2h = make_desc(smb + AQ2H);
                const uint64_t dq2l = make_desc(smb + AQ2L);
#pragma unroll
                for (int ks = 0; ks < 4; ks++) {
                    const uint64_t o = ks * 2;
                    mma_f16_ss(tmem + TM_S2, dq2h + o, dkh + o, idescS, ks > 0 ? 1u : 0u);
                    mma_f16_ss(tmem + TM_S2, dq2h + o, dkl + o, idescS, 1u);
                    mma_f16_ss(tmem + TM_S2, dq2l + o, dkh + o, idescS, 1u);
                }
                if (act1) {
                    const uint64_t dq1h = make_desc(smb + AQ1H);
                    const uint64_t dq1l = make_desc(smb + AQ1L);
#pragma unroll
                    for (int ks = 0; ks < 4; ks++) {
                        const uint64_t o = ks * 2;
                        mma_f16_ss(tmem + TM_S1, dq1h + o, dkh + o, idescS, ks > 0 ? 1u : 0u);
                        mma_f16_ss(tmem + TM_S1, dq1h + o, dkl + o, idescS, 1u);
                        mma_f16_ss(tmem + TM_S1, dq1l + o, dkh + o, idescS, 1u);
                    }
                }
                TC_COMMIT(smb + ATT_MBS);
            }
        }
        mbar_wait(smb + ATT_MBS, (uint32_t)(kt & 1));
        TC_FENCE_AFTER();

#pragma unroll
        for (int tsel = 0; tsel < 2; tsel++) {
            if (tsel == 1 && !act1) break;
            const uint32_t tms = (tsel == 0) ? (tmem + TM_S2) : (tmem + TM_S1);
            const bool diag = (kt == ((tsel == 0) ? qhi : qlo));
            float lsum = 0.f;
            uint32_t hibuf[2][16], lobuf[2][16];
#pragma unroll
            for (int half = 0; half < 2; half++) {
                uint32_t sv[32];
                LDTM_X32(sv, tms + cbase + half * 32);
                TC_WAIT_LD();
                const int keyblk = cbase + half * 32;
#pragma unroll
                for (int u = 0; u < 16; u++) {
                    const int c0 = u * 2;
                    float p0 = 0.f, p1 = 0.f;
                    if (!diag || (keyblk + c0 <= r))
                        p0 = __expf(__uint_as_float(sv[c0]) * 0.125f);
                    if (!diag || (keyblk + c0 + 1 <= r))
                        p1 = __expf(__uint_as_float(sv[c0 + 1]) * 0.125f);
                    lsum += p0 + p1;
                    __nv_bfloat16 h0 = __float2bfloat16(p0);
                    __nv_bfloat16 h1 = __float2bfloat16(p1);
                    hibuf[half][u] = pack_bf2(h0, h1);
                    lobuf[half][u] = pack_bf2(__float2bfloat16(p0 - __bfloat162float(h0)),
                                              __float2bfloat16(p1 - __bfloat162float(h1)));
                }
            }
#pragma unroll
            for (int half = 0; half < 2; half++) {
                const uint32_t hcol2 = (uint32_t)(cbase + half * 16);
                STTM_X16(tms + hcol2 + warpofs, hibuf[half]);
                STTM_X16(tms + 32 + hcol2 + warpofs, lobuf[half]);
            }
            if (tsel == 0) lacc2 += lsum; else lacc1 += lsum;
        }
        TC_WAIT_ST();
        TC_FENCE_BEFORE();
        __syncthreads();

        if (wid == 0) {
            TC_FENCE_AFTER();
            if (elect_one()) {
                const uint64_t dvh = make_desc(smb + VH);
                const uint64_t dvl = make_desc(smb + VL);
#pragma unroll
                for (int ks = 0; ks < 8; ks++) {
                    const uint64_t bo = (ks < 4) ? (uint64_t)(ks * 2) : (uint64_t)(512 + (ks - 4) * 2);
                    const uint32_t aoh = (uint32_t)(((ks >> 2) * 64) + (ks & 3) * 8);
                    const uint32_t ph2 = tmem + TM_S2 + aoh;
                    const uint32_t pl2 = tmem + TM_S2 + 32 + aoh;
                    mma_f16_ts(tmem + TM_O2, ph2, dvh + bo, idescO, (kt > 0 || ks > 0) ? 1u : 0u);
                    mma_f16_ts(tmem + TM_O2, ph2, dvl + bo, idescO, 1u);
                    mma_f16_ts(tmem + TM_O2, pl2, dvh + bo, idescO, 1u);
                }
                if (act1) {
#pragma unroll
                    for (int ks = 0; ks < 8; ks++) {
                        const uint64_t bo = (ks < 4) ? (uint64_t)(ks * 2) : (uint64_t)(512 + (ks - 4) * 2);
                        const uint32_t aoh = (uint32_t)(((ks >> 2) * 64) + (ks & 3) * 8);
                        const uint32_t ph1 = tmem + TM_S1 + aoh;
                        const uint32_t pl1 = tmem + TM_S1 + 32 + aoh;
                        mma_f16_ts(tmem + TM_O1, ph1, dvh + bo, idescO, (kt > 0 || ks > 0) ? 1u : 0u);
                        mma_f16_ts(tmem + TM_O1, ph1, dvl + bo, idescO, 1u);
                        mma_f16_ts(tmem + TM_O1, pl1, dvh + bo, idescO, 1u);
                    }
                }
                TC_COMMIT(mbo);
            }
        }
    }

    {
        const uint32_t mbf = smb + (((nkt - 1) & 1) ? ATT_MBO1 : ATT_MBO0);
        mbar_wait(mbf, (uint32_t)(((nkt - 1) >> 1) & 1));
    }
    TC_FENCE_AFTER();

    float* ls = (float*)(smem + AQ1H);
    ls[(wid >> 2) * 128 + r] = lacc1;
    ls[256 + (wid >> 2) * 128 + r] = lacc2;
    __syncthreads();
    const float inv1 = 1.f / (ls[r] + ls[128 + r]);
    const float inv2 = 1.f / (ls[256 + r] + ls[384 + r]);

#pragma unroll
    for (int tsel = 0; tsel < 2; tsel++) {
        const uint32_t tmo = (tsel == 0) ? (tmem + TM_O2) : (tmem + TM_O1);
        const float inv = (tsel == 0) ? inv2 : inv1;
        const int qt = (tsel == 0) ? qhi : qlo;
        uint32_t ov[32];
        LDTM_X32(ov, tmo + (wid >> 2) * 32);
        TC_WAIT_LD();
        uint32_t hb[16], lb[16];
#pragma unroll
        for (int u = 0; u < 16; u++) {
            const float v0 = __uint_as_float(ov[2 * u]) * inv;
            const float v1 = __uint_as_float(ov[2 * u + 1]) * inv;
            __nv_bfloat16 h0 = __float2bfloat16(v0), h1 = __float2bfloat16(v1);
            hb[u] = pack_bf2(h0, h1);
            lb[u] = pack_bf2(__float2bfloat16(v0 - __bfloat162float(h0)),
                             __float2bfloat16(v1 - __bfloat162float(h1)));
        }
        const size_t o = ((size_t)b * SEQ + qt * 128 + r) * DMODEL + h * 64 + (wid >> 2) * 32;
#pragma unroll
        for (int u = 0; u < 4; u++) {
            *(uint4*)(g_AOhi + o + u * 8) = *(uint4*)&hb[u * 4];
            *(uint4*)(g_AOlo + o + u * 8) = *(uint4*)&lb[u * 4];
        }
    }
    TC_FENCE_BEFORE();
    __syncthreads();
    if (tid == 0) {
        MBAR_INVAL(smb + ATT_MBS);
        MBAR_INVAL(smb + ATT_MBO0);
        MBAR_INVAL(smb + ATT_MBO1);
    }
    if (wid == 0) TC_DEALLOC(tmem, 512);
#else
    // fallback (never selected at runtime)
    const int tid = threadIdx.x;
    if (tid < 128) {
        for (int tsel = 0; tsel < 2; tsel++) {
            const int qt = (tsel == 0) ? qhi : qlo;
            const int rq = qt * 128 + tid;
            const __nv_bfloat16* qh = Qh + (((size_t)b * NHEAD + h) * SEQ + rq) * HD;
            const __nv_bfloat16* ql = Ql + (((size_t)b * NHEAD + h) * SEQ + rq) * HD;
            float q[HD];
            for (int d = 0; d < HD; d++)
                q[d] = __bfloat162float(qh[d]) + __bfloat162float(ql[d]);
            float l = 0.f, o[HD];
            for (int d = 0; d < HD; d++) o[d] = 0.f;
            for (int s = 0; s <= rq; s++) {
                const __nv_bfloat16* kh = Kh + (((size_t)b * NKV + g) * SEQ + s) * HD;
                const __nv_bfloat16* kl = Kl + (((size_t)b * NKV + g) * SEQ + s) * HD;
                float sc = 0.f;
                for (int d = 0; d < HD; d++)
                    sc += q[d] * (__bfloat162float(kh[d]) + __bfloat162float(kl[d]));
                float pp = __expf(sc * 0.125f);
                l += pp;
                for (int d = 0; d < HD; d++) {
                    const size_t vo = (((size_t)b * NKV + g) * HD + d) * SEQ + s;
                    o[d] += pp * (__bfloat162float(Vth[vo]) + __bfloat162float(Vtl[vo]));
                }
            }
            for (int d = 0; d < HD; d++) {
                const float vv = o[d] / l;
                __nv_bfloat16 hh = __float2bfloat16(vv);
                const size_t oo = ((size_t)b * SEQ + rq) * DMODEL + h * 64 + d;
                g_AOhi[oo] = hh;
                g_AOlo[oo] = __float2bfloat16(vv - __bfloat162float(hh));
            }
        }
    }
#endif
}

// ---------------- launch -----------------------------------------------------------
extern "C" void kernel_launch(void* const* d_in, const int* in_sizes, int n_in,
                              void* d_out, int out_size)
{
    const float* x   = (const float*)d_in[0];
    const int*   pos = (const int*)  d_in[1];
    const float* q_w = (const float*)d_in[2];
    const float* q_b = (const float*)d_in[3];
    const float* k_w = (const float*)d_in[4];
    const float* k_b = (const float*)d_in[5];
    const float* v_w = (const float*)d_in[6];
    const float* v_b = (const float*)d_in[7];
    const float* o_w = (const float*)d_in[8];
    const float* o_b = (const float*)d_in[9];
    float* out = (float*)d_out;

    float* Vp;
    __nv_bfloat16 *Whi, *Wlo, *Xhi, *Xlo, *AOhi, *AOlo;
    __nv_bfloat16 *Qhb, *Qlb, *Khb, *Klb, *Vthb, *Vtlb;
    cudaGetSymbolAddress((void**)&Vp, g_Vp);
    cudaGetSymbolAddress((void**)&Whi, g_Whi);
    cudaGetSymbolAddress((void**)&Wlo, g_Wlo);
    cudaGetSymbolAddress((void**)&Xhi, g_Xhi);
    cudaGetSymbolAddress((void**)&Xlo, g_Xlo);
    cudaGetSymbolAddress((void**)&AOhi, g_AOhi);
    cudaGetSymbolAddress((void**)&AOlo, g_AOlo);
    cudaGetSymbolAddress((void**)&Qhb, g_Qhb);
    cudaGetSymbolAddress((void**)&Qlb, g_Qlb);
    cudaGetSymbolAddress((void**)&Khb, g_Khb);
    cudaGetSymbolAddress((void**)&Klb, g_Klb);
    cudaGetSymbolAddress((void**)&Vthb, g_Vthb);
    cudaGetSymbolAddress((void**)&Vtlb, g_Vtlb);

    cudaFuncSetAttribute(gemm_tc_kernel,
                         cudaFuncAttributeMaxDynamicSharedMemorySize, GSM_TOTAL);
    cudaFuncSetAttribute(attn_tc_kernel,
                         cudaFuncAttributeMaxDynamicSharedMemorySize, ATT_TOTAL);

    wsplit_all_kernel<<<dim3(24, 64), dim3(32, 8)>>>(q_w, k_w, v_w, o_w);
    asplit_kernel<<<(MROWS * KDIM / 4) / 256, 256>>>(x, Xhi, Xlo);
    ropetab_kernel<<<SEQ, 32>>>(pos);
    // fused QKV projection: 128x256 tiles, grid (1280/256=5, 64)
    gemm_tc_kernel<<<dim3(NQKV / 256, MROWS / 128), 256, GSM_TOTAL>>>(
        Xhi, Xlo, Whi + WQ_OFF, Wlo + WQ_OFF, q_b, k_b, v_b, Vp, NQKV, 1);
    vtsplit_kernel<<<dim3(SEQ / 32, HD / 32, BATCH * NKV), dim3(32, 8)>>>(Vp, Vthb, Vtlb);
    attn_tc_kernel<<<dim3(SEQ / 256, NHEAD, BATCH), 256, ATT_TOTAL>>>(
        Qhb, Qlb, Khb, Klb, Vthb, Vtlb);
    // output projection: grid (768/256=3, 64)
    gemm_tc_kernel<<<dim3(768 / 256, MROWS / 128), 256, GSM_TOTAL>>>(
        AOhi, AOlo, Whi + WO_OFF, Wlo + WO_OFF, o_b, o_b, o_b, out, 768, 0);
}

// round 17
// speedup vs baseline: 1.0732x; 1.0732x over previous
#include <cuda_runtime.h>
#include <cuda_bf16.h>
#include <math.h>
#include <stdint.h>

#define BATCH 8
#define SEQ   1024
#define DMODEL 768
#define NHEAD 12
#define NKV   4
#define NREP  3
#define HD    64
#define MROWS (BATCH*SEQ)   // 8192
#define KDIM  768
#define NQKV  1280          // 768 + 256 + 256

#if defined(__CUDA_ARCH__) && (defined(__CUDA_ARCH_FEAT_SM103_ALL) || defined(__CUDA_ARCH_FEAT_SM100_ALL) || defined(__CUDA_ARCH_SPECIFIC__))
#define GQA_TCGEN05 1
#else
#define GQA_TCGEN05 0
#endif

// ---------------- scratch ----------------
__device__ __align__(256) float g_Vp[MROWS * 256];
__device__ __align__(256) __nv_bfloat16 g_Xhi[MROWS * KDIM];
__device__ __align__(256) __nv_bfloat16 g_Xlo[MROWS * KDIM];
__device__ __align__(256) __nv_bfloat16 g_AOhi[MROWS * KDIM];
__device__ __align__(256) __nv_bfloat16 g_AOlo[MROWS * KDIM];
__device__ __align__(256) __nv_bfloat16 g_Qhb[BATCH * NHEAD * SEQ * HD];
__device__ __align__(256) __nv_bfloat16 g_Qlb[BATCH * NHEAD * SEQ * HD];
__device__ __align__(256) __nv_bfloat16 g_Khb[BATCH * NKV * SEQ * HD];
__device__ __align__(256) __nv_bfloat16 g_Klb[BATCH * NKV * SEQ * HD];
__device__ __align__(256) __nv_bfloat16 g_Vthb[BATCH * NKV * HD * SEQ];
__device__ __align__(256) __nv_bfloat16 g_Vtlb[BATCH * NKV * HD * SEQ];
__device__ __align__(256) float g_cost[SEQ * 32];
__device__ __align__(256) float g_sint[SEQ * 32];
#define WQ_OFF 0
#define WK_OFF (768*768)
#define WV_OFF (WK_OFF + 256*768)
#define WO_OFF (WV_OFF + 256*768)
#define WT_TOT (WO_OFF + 768*768)
__device__ __align__(256) __nv_bfloat16 g_Whi[WT_TOT];
__device__ __align__(256) __nv_bfloat16 g_Wlo[WT_TOT];

// ---------------- ptx helpers ----------------
__device__ __forceinline__ uint32_t smem_u32(const void* p) {
    uint32_t a;
    asm("{ .reg .u64 t; cvta.to.shared.u64 t, %1; cvt.u32.u64 %0, t; }" : "=r"(a) : "l"(p));
    return a;
}
#if GQA_TCGEN05
__device__ __forceinline__ uint32_t elect_one() {
    uint32_t p;
    asm volatile("{\n\t.reg .pred p;\n\telect.sync _|p, 0xFFFFFFFF;\n\tselp.b32 %0, 1, 0, p;\n\t}" : "=r"(p));
    return p;
}
__device__ __forceinline__ void mma_f16_ss(uint32_t d, uint64_t ad, uint64_t bd,
                                           uint32_t idesc, uint32_t acc) {
    asm volatile(
        "{\n\t.reg .pred p;\n\tsetp.ne.u32 p, %5, 0;\n\t"
        "tcgen05.mma.cta_group::1.kind::f16 [%0], %1, %2, %3, {%4, %4, %4, %4}, p;\n\t}"
        :: "r"(d), "l"(ad), "l"(bd), "r"(idesc), "r"(0u), "r"(acc) : "memory");
}
__device__ __forceinline__ void mma_f16_ts(uint32_t d, uint32_t a_tmem, uint64_t bd,
                                           uint32_t idesc, uint32_t acc) {
    asm volatile(
        "{\n\t.reg .pred p;\n\tsetp.ne.u32 p, %5, 0;\n\t"
        "tcgen05.mma.cta_group::1.kind::f16 [%0], [%1], %2, %3, {%4, %4, %4, %4}, p;\n\t}"
        :: "r"(d), "r"(a_tmem), "l"(bd), "r"(idesc), "r"(0u), "r"(acc) : "memory");
}
__device__ __forceinline__ void cp16(uint32_t dst, const void* src) {
    asm volatile("cp.async.cg.shared.global [%0], [%1], 16;" :: "r"(dst), "l"(src) : "memory");
}
#define CP_COMMIT() asm volatile("cp.async.commit_group;" ::: "memory")
#define CP_WAIT(n)  asm volatile("cp.async.wait_group %0;" :: "n"(n) : "memory")
#define TC_ALLOC(sm, n)   asm volatile("tcgen05.alloc.cta_group::1.sync.aligned.shared::cta.b32 [%0], %1;" :: "r"(sm), "r"(n) : "memory")
#define TC_RELINQ()       asm volatile("tcgen05.relinquish_alloc_permit.cta_group::1.sync.aligned;")
#define TC_DEALLOC(t, n)  asm volatile("tcgen05.dealloc.cta_group::1.sync.aligned.b32 %0, %1;" :: "r"(t), "r"(n))
#define TC_COMMIT(mb)     asm volatile("tcgen05.commit.cta_group::1.mbarrier::arrive::one.shared::cluster.b64 [%0];" :: "r"(mb) : "memory")
#define TC_WAIT_LD()      asm volatile("tcgen05.wait::ld.sync.aligned;" ::: "memory")
#define TC_WAIT_ST()      asm volatile("tcgen05.wait::st.sync.aligned;" ::: "memory")
#define TC_FENCE_AFTER()  asm volatile("tcgen05.fence::after_thread_sync;" ::: "memory")
#define TC_FENCE_BEFORE() asm volatile("tcgen05.fence::before_thread_sync;" ::: "memory")
#define MBAR_INIT(mb, c)  asm volatile("mbarrier.init.shared.b64 [%0], %1;" :: "r"(mb), "r"(c) : "memory")
#define MBAR_INVAL(mb)    asm volatile("mbarrier.inval.shared.b64 [%0];" :: "r"(mb) : "memory")
#define FENCE_ASYNC()     asm volatile("fence.proxy.async.shared::cta;" ::: "memory")

__device__ __forceinline__ void mbar_wait(uint32_t mb, uint32_t parity) {
    asm volatile(
        "{\n\t.reg .pred P1;\n\t"
        "WAIT_LOOP_%=:\n\t"
        "mbarrier.try_wait.parity.acquire.cta.shared::cta.b64 P1, [%0], %1, 0x989680;\n\t"
        "@P1 bra.uni WAIT_DONE_%=;\n\t"
        "bra.uni WAIT_LOOP_%=;\n\t"
        "WAIT_DONE_%=:\n\t}"
        :: "r"(mb), "r"(parity) : "memory");
}
#define LDTM_X32(r, addr) \
    asm volatile("tcgen05.ld.sync.aligned.32x32b.x32.b32 " \
        "{%0,%1,%2,%3,%4,%5,%6,%7,%8,%9,%10,%11,%12,%13,%14,%15," \
        "%16,%17,%18,%19,%20,%21,%22,%23,%24,%25,%26,%27,%28,%29,%30,%31}, [%32];" \
        : "=r"((r)[0]),"=r"((r)[1]),"=r"((r)[2]),"=r"((r)[3]),"=r"((r)[4]),"=r"((r)[5]),"=r"((r)[6]),"=r"((r)[7]), \
          "=r"((r)[8]),"=r"((r)[9]),"=r"((r)[10]),"=r"((r)[11]),"=r"((r)[12]),"=r"((r)[13]),"=r"((r)[14]),"=r"((r)[15]), \
          "=r"((r)[16]),"=r"((r)[17]),"=r"((r)[18]),"=r"((r)[19]),"=r"((r)[20]),"=r"((r)[21]),"=r"((r)[22]),"=r"((r)[23]), \
          "=r"((r)[24]),"=r"((r)[25]),"=r"((r)[26]),"=r"((r)[27]),"=r"((r)[28]),"=r"((r)[29]),"=r"((r)[30]),"=r"((r)[31]) \
        : "r"(addr))
#define STTM_X16(addr, r) \
    asm volatile("tcgen05.st.sync.aligned.32x32b.x16.b32 [%0], " \
        "{%1,%2,%3,%4,%5,%6,%7,%8,%9,%10,%11,%12,%13,%14,%15,%16};" \
        :: "r"(addr), \
           "r"((r)[0]),"r"((r)[1]),"r"((r)[2]),"r"((r)[3]),"r"((r)[4]),"r"((r)[5]),"r"((r)[6]),"r"((r)[7]), \
           "r"((r)[8]),"r"((r)[9]),"r"((r)[10]),"r"((r)[11]),"r"((r)[12]),"r"((r)[13]),"r"((r)[14]),"r"((r)[15]) \
        : "memory")
#endif // GQA_TCGEN05

__device__ __forceinline__ uint32_t sw128(uint32_t b) { return b ^ ((b >> 3) & 0x70); }
__device__ __forceinline__ uint64_t make_desc(uint32_t addr) {
    const uint64_t base = (uint64_t(2) << 61) | (uint64_t(1) << 46) |
                          (uint64_t(64) << 32) | (uint64_t(1) << 16);
    return base | ((uint64_t)(addr >> 4) & 0x3FFF);
}
__device__ __forceinline__ uint32_t pack_bf2(__nv_bfloat16 a, __nv_bfloat16 b) {
    __nv_bfloat162 t; t.x = a; t.y = b;
    return *(uint32_t*)&t;
}

// ---------------- merged weight prep ----------------
__global__ void wsplit_all_kernel(const float* __restrict__ qw, const float* __restrict__ kw,
                                  const float* __restrict__ vw, const float* __restrict__ ow)
{
    __shared__ float t[32][33];
    const int tx = threadIdx.x, ty = threadIdx.y;
    const int k0 = blockIdx.x * 32;
    const int nt = blockIdx.y;
    const float* W; int N, off, n0;
    if (nt < 24)      { W = qw; N = 768; off = WQ_OFF; n0 = nt * 32; }
    else if (nt < 32) { W = kw; N = 256; off = WK_OFF; n0 = (nt - 24) * 32; }
    else if (nt < 40) { W = vw; N = 256; off = WV_OFF; n0 = (nt - 32) * 32; }
    else              { W = ow; N = 768; off = WO_OFF; n0 = (nt - 40) * 32; }
#pragma unroll
    for (int i = ty; i < 32; i += 8)
        t[i][tx] = W[(size_t)(k0 + i) * N + n0 + tx];
    __syncthreads();
#pragma unroll
    for (int i = ty; i < 32; i += 8) {
        float v = t[tx][i];
        __nv_bfloat16 h = __float2bfloat16(v);
        __nv_bfloat16 l = __float2bfloat16(v - __bfloat162float(h));
        g_Whi[off + (size_t)(n0 + i) * KDIM + k0 + tx] = h;
        g_Wlo[off + (size_t)(n0 + i) * KDIM + k0 + tx] = l;
    }
}

// ---------------- activation split ----------------
__global__ __launch_bounds__(256) void asplit_kernel(
    const float* __restrict__ in, __nv_bfloat16* __restrict__ hi,
    __nv_bfloat16* __restrict__ lo)
{
    const size_t i = (size_t)blockIdx.x * 256 + threadIdx.x;
    float4 v = ((const float4*)in)[i];
    __nv_bfloat16 h0 = __float2bfloat16(v.x), h1 = __float2bfloat16(v.y);
    __nv_bfloat16 h2 = __float2bfloat16(v.z), h3 = __float2bfloat16(v.w);
    __nv_bfloat16 l0 = __float2bfloat16(v.x - __bfloat162float(h0));
    __nv_bfloat16 l1 = __float2bfloat16(v.y - __bfloat162float(h1));
    __nv_bfloat16 l2 = __float2bfloat16(v.z - __bfloat162float(h2));
    __nv_bfloat16 l3 = __float2bfloat16(v.w - __bfloat162float(h3));
    ((uint2*)hi)[i] = make_uint2(pack_bf2(h0, h1), pack_bf2(h2, h3));
    ((uint2*)lo)[i] = make_uint2(pack_bf2(l0, l1), pack_bf2(l2, l3));
}

// ---------------- RoPE table ----------------
__global__ void ropetab_kernel(const int* __restrict__ pos)
{
    const int t = blockIdx.x, j = threadIdx.x;
    const float LOG2_10000_OVER_32 = 0.41524101186092f;
    float th = (float)pos[t] * exp2f(-(float)j * LOG2_10000_OVER_32);
    float s, c;
    sincosf(th, &s, &c);
    g_cost[t * 32 + j] = c;
    g_sint[t * 32 + j] = s;
}

// ---------------- V transpose + split ----------------
__global__ void vtsplit_kernel(const float* __restrict__ Vp,
                               __nv_bfloat16* __restrict__ Vth,
                               __nv_bfloat16* __restrict__ Vtl)
{
    __shared__ float t[32][33];
    const int tx = threadIdx.x, ty = threadIdx.y;
    const int t0 = blockIdx.x * 32, d0 = blockIdx.y * 32;
    const int b = blockIdx.z >> 2, g = blockIdx.z & 3;
#pragma unroll
    for (int i = ty; i < 32; i += 8)
        t[i][tx] = Vp[((size_t)b * SEQ + t0 + i) * 256 + g * HD + d0 + tx];
    __syncthreads();
#pragma unroll
    for (int i = ty; i < 32; i += 8) {
        float v = t[tx][i];
        __nv_bfloat16 h = __float2bfloat16(v);
        __nv_bfloat16 l = __float2bfloat16(v - __bfloat162float(h));
        const size_t o = (((size_t)b * NKV + g) * HD + d0 + i) * SEQ + t0 + tx;
        Vth[o] = h; Vtl[o] = l;
    }
}

// ---------------- tcgen05 GEMM: 3-stage cp.async, overlapped stage-reuse (R14) -----
#define NCHUNK   (KDIM/64)        // 12
#define GSM_MB0  16
#define GSM_TILE 16384
#define GSM_STAGE (4*GSM_TILE)              // 64KB per stage
#define GSM_TOTAL (1024 + 3*GSM_STAGE)      // 197632 bytes

__global__ __launch_bounds__(256) void gemm_tc_kernel(
    const __nv_bfloat16* __restrict__ Ahi, const __nv_bfloat16* __restrict__ Alo,
    const __nv_bfloat16* __restrict__ Bhi, const __nv_bfloat16* __restrict__ Blo,
    const float* __restrict__ bq, const float* __restrict__ bk,
    const float* __restrict__ bv, float* __restrict__ C, int Ntot, int mode)
{
#if GQA_TCGEN05
    extern __shared__ char smem[];
    const uint32_t smb = smem_u32(smem);
    const int tid = threadIdx.x;
    const int wid = tid >> 5, lane = tid & 31;

    if (wid == 0) { TC_ALLOC(smb, 128); TC_RELINQ(); }
    if (tid == 0) {
        MBAR_INIT(smb + GSM_MB0, 1);
        MBAR_INIT(smb + GSM_MB0 + 8, 1);
        MBAR_INIT(smb + GSM_MB0 + 16, 1);
    }
    __syncthreads();
    uint32_t tmem;
    asm volatile("ld.shared.b32 %0, [%1];" : "=r"(tmem) : "r"(smb));

    const int brow = blockIdx.y * 128;
    const int bcol = blockIdx.x * 128;
    const __nv_bfloat16* Ahp = Ahi + (size_t)brow * KDIM;
    const __nv_bfloat16* Alp = Alo + (size_t)brow * KDIM;
    const __nv_bfloat16* Bhp = Bhi + (size_t)bcol * KDIM;
    const __nv_bfloat16* Blp = Blo + (size_t)bcol * KDIM;

    const uint32_t idesc = (1u << 4) | (1u << 7) | (1u << 10) |
                           ((128u / 8) << 17) | ((128u / 16) << 24);

    auto fill_chunk = [&](int ch, int st) {
        const uint32_t sa = smb + 1024 + (uint32_t)st * GSM_STAGE;
        const int kc0 = ch * 64;
#pragma unroll
        for (int j = 0; j < 4; j++) {
            const int idx = j * 256 + tid;
            const int row = idx >> 3, c8 = (idx & 7) << 3;
            const uint32_t sw = sw128(row * 128 + c8 * 2);
            const size_t go = (size_t)row * KDIM + kc0 + c8;
            cp16(sa + sw,                Ahp + go);
            cp16(sa + GSM_TILE + sw,     Alp + go);
            cp16(sa + 2 * GSM_TILE + sw, Bhp + go);
            cp16(sa + 3 * GSM_TILE + sw, Blp + go);
        }
    };

    fill_chunk(0, 0); CP_COMMIT();
    fill_chunk(1, 1); CP_COMMIT();

    for (int ch = 0; ch < NCHUNK; ch++) {
        const int st = ch % 3;
        CP_WAIT(1);
        FENCE_ASYNC();
        __syncthreads();

        if (wid == 0) {
            if (elect_one()) {
                const uint32_t sa = smb + 1024 + (uint32_t)st * GSM_STAGE;
                const uint64_t dah = make_desc(sa);
                const uint64_t dal = make_desc(sa + GSM_TILE);
                const uint64_t dbh = make_desc(sa + 2 * GSM_TILE);
                const uint64_t dbl = make_desc(sa + 3 * GSM_TILE);
#pragma unroll
                for (int ks = 0; ks < 4; ks++) {
                    const uint64_t o = ks * 2;
                    mma_f16_ss(tmem, dah + o, dbh + o, idesc, (ch > 0 || ks > 0) ? 1u : 0u);
                    mma_f16_ss(tmem, dah + o, dbl + o, idesc, 1u);
                    mma_f16_ss(tmem, dal + o, dbh + o, idesc, 1u);
                }
                TC_COMMIT(smb + GSM_MB0 + (uint32_t)st * 8);
            }
        }

        const int nxt = ch + 2;
        if (nxt < NCHUNK) {
            if (ch >= 1)
                mbar_wait(smb + GSM_MB0 + (uint32_t)((ch - 1) % 3) * 8,
                          (uint32_t)(((ch - 1) / 3) & 1));
            fill_chunk(nxt, nxt % 3);
        }
        CP_COMMIT();
    }

    mbar_wait(smb + GSM_MB0 + (uint32_t)((NCHUNK - 1) % 3) * 8,
              (uint32_t)(((NCHUNK - 1) / 3) & 1));
    TC_FENCE_AFTER();

    const int m = brow + (wid & 3) * 32 + lane;
    const int ch2 = (wid >> 2) * 64;
    const int hcol = bcol + ch2;

    float val[64];
#pragma unroll
    for (int half = 0; half < 2; half++) {
        uint32_t r[32];
        LDTM_X32(r, tmem + ch2 + half * 32);
        TC_WAIT_LD();
#pragma unroll
        for (int i = 0; i < 32; i++) {
            const int cc = hcol + half * 32 + i;
            const float bb = (cc < 768) ? bq[cc] : ((cc < 1024) ? bk[cc - 768] : bv[cc - 1024]);
            val[half * 32 + i] = __uint_as_float(r[i]) + bb;
        }
    }

    if (mode == 0) {
#pragma unroll
        for (int u = 0; u < 16; u++)
            *(float4*)&C[(size_t)m * Ntot + hcol + u * 4] = *(float4*)&val[u * 4];
    } else {
        const int b_ = m >> 10, t_ = m & (SEQ - 1);
        if (hcol >= 1024) {
            float* dst = g_Vp + (size_t)m * 256 + (hcol - 1024);
#pragma unroll
            for (int u = 0; u < 16; u++)
                *(float4*)(dst + u * 4) = *(float4*)&val[u * 4];
        } else {
            float ct[32], st2[32];
            const float* cb = g_cost + t_ * 32;
            const float* sb = g_sint + t_ * 32;
#pragma unroll
            for (int u = 0; u < 8; u++) {
                *(float4*)&ct[u * 4] = *(const float4*)&cb[u * 4];
                *(float4*)&st2[u * 4] = *(const float4*)&sb[u * 4];
            }
            __nv_bfloat16 *dh, *dl;
            if (hcol < 768) {
                const int hh = hcol >> 6;
                const size_t o = (((size_t)b_ * NHEAD + hh) * SEQ + t_) * HD;
                dh = g_Qhb + o; dl = g_Qlb + o;
            } else {
                const int gg = (hcol - 768) >> 6;
                const size_t o = (((size_t)b_ * NKV + gg) * SEQ + t_) * HD;
                dh = g_Khb + o; dl = g_Klb + o;
            }
            {
                uint32_t hb[16], lb[16];
#pragma unroll
                for (int u = 0; u < 16; u++) {
                    const int k0 = 2 * u, k1 = 2 * u + 1;
                    const float r0 = val[k0] * ct[k0] - val[16 + u] * st2[k0];
                    const float r1 = val[k1] * ct[k1] - val[48 + u] * st2[k1];
                    __nv_bfloat16 h0 = __float2bfloat16(r0), h1 = __float2bfloat16(r1);
                    hb[u] = pack_bf2(h0, h1);
                    lb[u] = pack_bf2(__float2bfloat16(r0 - __bfloat162float(h0)),
                                     __float2bfloat16(r1 - __bfloat162float(h1)));
                }
#pragma unroll
                for (int u = 0; u < 4; u++) {
                    *(uint4*)(dh + u * 8) = *(uint4*)&hb[u * 4];
                    *(uint4*)(dl + u * 8) = *(uint4*)&lb[u * 4];
                }
            }
            {
                uint32_t hb[16], lb[16];
#pragma unroll
                for (int u = 0; u < 16; u++) {
                    const int j0 = 2 * u, j1 = 2 * u + 1;
                    const float r0 = val[32 + j0] * ct[j0] + val[u] * st2[j0];
                    const float r1 = val[32 + j1] * ct[j1] + val[32 + u] * st2[j1];
                    __nv_bfloat16 h0 = __float2bfloat16(r0), h1 = __float2bfloat16(r1);
                    hb[u] = pack_bf2(h0, h1);
                    lb[u] = pack_bf2(__float2bfloat16(r0 - __bfloat162float(h0)),
                                     __float2bfloat16(r1 - __bfloat162float(h1)));
                }
#pragma unroll
                for (int u = 0; u < 4; u++) {
                    *(uint4*)(dh + 32 + u * 8) = *(uint4*)&hb[u * 4];
                    *(uint4*)(dl + 32 + u * 8) = *(uint4*)&lb[u * 4];
                }
            }
        }
    }
    TC_FENCE_BEFORE();
    __syncthreads();
    if (tid == 0) {
        MBAR_INVAL(smb + GSM_MB0);
        MBAR_INVAL(smb + GSM_MB0 + 8);
        MBAR_INVAL(smb + GSM_MB0 + 16);
    }
    if (wid == 0) TC_DEALLOC(tmem, 128);
#else
    const int brow = blockIdx.y * 128, bcol = blockIdx.x * 128;
    if ((int)threadIdx.x >= 128) return;
    const int row = brow + (int)threadIdx.x;
    float acc[128];
    for (int c = 0; c < 128; c++) {
        const int col = bcol + c;
        float a_ = 0.f;
        for (int k = 0; k < KDIM; k++) {
            float a = __bfloat162float(Ahi[(size_t)row * KDIM + k]) +
                      __bfloat162float(Alo[(size_t)row * KDIM + k]);
            float w = __bfloat162float(Bhi[(size_t)col * KDIM + k]) +
                      __bfloat162float(Blo[(size_t)col * KDIM + k]);
            a_ += a * w;
        }
        float bb = (col < 768) ? bq[col] : ((col < 1024) ? bk[col - 768] : bv[col - 1024]);
        acc[c] = a_ + bb;
    }
    if (mode == 0) {
        for (int c = 0; c < 128; c++) C[(size_t)row * Ntot + bcol + c] = acc[c];
    } else {
        const int b_ = row >> 10, t_ = row & (SEQ - 1);
        for (int hc = 0; hc < 2; hc++) {
            const int hcol = bcol + hc * 64;
            float* v = acc + hc * 64;
            if (hcol >= 1024) {
                for (int k = 0; k < 64; k++) g_Vp[(size_t)row * 256 + (hcol - 1024) + k] = v[k];
            } else {
                __nv_bfloat16 *dh, *dl;
                if (hcol < 768) {
                    const size_t o = (((size_t)b_ * NHEAD + (hcol >> 6)) * SEQ + t_) * HD;
                    dh = g_Qhb + o; dl = g_Qlb + o;
                } else {
                    const size_t o = (((size_t)b_ * NKV + ((hcol - 768) >> 6)) * SEQ + t_) * HD;
                    dh = g_Khb + o; dl = g_Klb + o;
                }
                for (int k = 0; k < 64; k++) {
                    const int j = k & 31;
                    float ctv = g_cost[t_ * 32 + j], stv = g_sint[t_ * 32 + j];
                    float res;
                    if (k < 32) {
                        const int pidx = (k & 1) ? 48 + (k >> 1) : 16 + (k >> 1);
                        res = v[k] * ctv - v[pidx] * stv;
                    } else {
                        const int pidx = (j & 1) ? 32 + (j >> 1) : (j >> 1);
                        res = v[k] * ctv + v[pidx] * stv;
                    }
                    __nv_bfloat16 h = __float2bfloat16(res);
                    dh[k] = h;
                    dl[k] = __float2bfloat16(res - __bfloat162float(h));
                }
            }
        }
    }
#endif
}

// ---------------- tcgen05 flash attention: prefetched K/V double-buffer ------------
// Fill(kt+1) is issued right after S(kt) completion is confirmed: tcgen05 executes
// in order, so S(kt)-done implies O(kt-1)-done, which is the last reader of stage
// (kt+1)&1. The fill then overlaps softmax+O-MMA+S(kt+1) before CP_WAIT sees it.
#define ATT_MBS  16
#define ATT_MBO0 24
#define ATT_MBO1 32
#define AQ1H 1024
#define AQ1L (AQ1H + 16384)
#define AQ2H (AQ1L + 16384)
#define AQ2L (AQ2H + 16384)
#define AKV0 (AQ2L + 16384)
#define ATT_TOTAL (AKV0 + 2*65536)   // 197632 bytes
#define TM_S1 0
#define TM_S2 128
#define TM_O1 256
#define TM_O2 320

__global__ __launch_bounds__(256) void attn_tc_kernel(
    const __nv_bfloat16* __restrict__ Qh, const __nv_bfloat16* __restrict__ Ql,
    const __nv_bfloat16* __restrict__ Kh, const __nv_bfloat16* __restrict__ Kl,
    const __nv_bfloat16* __restrict__ Vth, const __nv_bfloat16* __restrict__ Vtl)
{
    const int p = blockIdx.x, h = blockIdx.y, b = blockIdx.z;
    const int g = h / NREP;
    const int qlo = p, qhi = (SEQ / 128 - 1) - p;
#if GQA_TCGEN05
    extern __shared__ char smem[];
    const uint32_t smb = smem_u32(smem);
    const int tid = threadIdx.x;
    const int wid = tid >> 5, lane = tid & 31;

    if (wid == 0) { TC_ALLOC(smb, 512); TC_RELINQ(); }
    if (tid == 0) {
        MBAR_INIT(smb + ATT_MBS, 1);
        MBAR_INIT(smb + ATT_MBO0, 1);
        MBAR_INIT(smb + ATT_MBO1, 1);
    }
    __syncthreads();
    uint32_t tmem;
    asm volatile("ld.shared.b32 %0, [%1];" : "=r"(tmem) : "r"(smb));

    const __nv_bfloat16* Khp = Kh + ((size_t)b * NKV + g) * SEQ * HD;
    const __nv_bfloat16* Klp = Kl + ((size_t)b * NKV + g) * SEQ * HD;
    const __nv_bfloat16* Vhp = Vth + ((size_t)b * NKV + g) * HD * SEQ;
    const __nv_bfloat16* Vlp = Vtl + ((size_t)b * NKV + g) * HD * SEQ;

    auto fill_kv = [&](int kt) {
        const uint32_t KH = AKV0 + (uint32_t)(kt & 1) * 65536;
        const uint32_t KL = KH + 16384, VH = KH + 32768, VL = KH + 49152;
#pragma unroll
        for (int j = 0; j < 4; j++) {
            const int idx = j * 256 + tid;
            const int row = idx >> 3, c8 = (idx & 7) << 3;
            const uint32_t sw = sw128(row * 128 + c8 * 2);
            const size_t go = (size_t)(kt * 128 + row) * HD + c8;
            cp16(smb + KH + sw, Khp + go);
            cp16(smb + KL + sw, Klp + go);
            const int d = idx >> 4, vch = idx & 15;
            const int key0 = vch * 8;
            const uint32_t voff = ((key0 & 64) ? 8192u : 0u) + d * 128 + (key0 & 63) * 2;
            const uint32_t vsw = sw128(voff);
            const size_t vgo = (size_t)d * SEQ + kt * 128 + key0;
            cp16(smb + VH + vsw, Vhp + vgo);
            cp16(smb + VL + vsw, Vlp + vgo);
        }
    };

    // prologue: Q tiles + K/V(0)
    {
        const __nv_bfloat16* q1h = Qh + (((size_t)b * NHEAD + h) * SEQ + qlo * 128) * HD;
        const __nv_bfloat16* q1l = Ql + (((size_t)b * NHEAD + h) * SEQ + qlo * 128) * HD;
        const __nv_bfloat16* q2h = Qh + (((size_t)b * NHEAD + h) * SEQ + qhi * 128) * HD;
        const __nv_bfloat16* q2l = Ql + (((size_t)b * NHEAD + h) * SEQ + qhi * 128) * HD;
#pragma unroll
        for (int j = 0; j < 4; j++) {
            const int idx = j * 256 + tid;
            const int row = idx >> 3, c8 = (idx & 7) << 3;
            const uint32_t sw = sw128(row * 128 + c8 * 2);
            const size_t go = (size_t)row * HD + c8;
            cp16(smb + AQ1H + sw, q1h + go);
            cp16(smb + AQ1L + sw, q1l + go);
            cp16(smb + AQ2H + sw, q2h + go);
            cp16(smb + AQ2L + sw, q2l + go);
        }
        CP_COMMIT();
        fill_kv(0);
        CP_COMMIT();
    }

    const int r = (wid & 3) * 32 + lane;
    const int cbase = (wid >> 2) * 64;
    const uint32_t warpofs = (uint32_t)(wid & 3) << 21;
    float lacc1 = 0.f, lacc2 = 0.f;

    const uint32_t idescS = (1u << 4) | (1u << 7) | (1u << 10) | (16u << 17) | (8u << 24);
    const uint32_t idescO = (1u << 4) | (1u << 7) | (1u << 10) | (8u << 17)  | (8u << 24);

    const int nkt = qhi + 1;
    for (int kt = 0; kt < nkt; kt++) {
        const bool act1 = (kt <= qlo);
        const int sb = kt & 1;
        const uint32_t mbo = smb + (sb ? ATT_MBO1 : ATT_MBO0);
        const uint32_t KH = AKV0 + (uint32_t)sb * 65536;
        const uint32_t VH = KH + 32768, VL = KH + 49152;

        // K/V(kt) was prefetched (prologue or previous iteration); wait for it.
        CP_WAIT(0);
        FENCE_ASYNC();
        __syncthreads();

        // S MMAs (SS)
        if (wid == 0) {
            if (elect_one()) {
                const uint64_t dkh = make_desc(KH ? (smb + KH) : 0);   // keep reg live
                const uint64_t dkl = make_desc(smb + KH + 16384);
                const uint64_t dkh2 = make_desc(smb + KH);
                const uint64_t dq2h = make_desc(smb + AQ2H);
                const uint64_t dq2l = make_desc(smb + AQ2L);
#pragma unroll
                for (int ks = 0; ks < 4; ks++) {
                    const uint64_t o = ks * 2;
                    mma_f16_ss(tmem + TM_S2, dq2h + o, dkh2 + o, idescS, ks > 0 ? 1u : 0u);
                    mma_f16_ss(tmem + TM_S2, dq2h + o, dkl + o, idescS, 1u);
                    mma_f16_ss(tmem + TM_S2, dq2l + o, dkh2 + o, idescS, 1u);
                }
                if (act1) {
                    const uint64_t dq1h = make_desc(smb + AQ1H);
                    const uint64_t dq1l = make_desc(smb + AQ1L);
#pragma unroll
                    for (int ks = 0; ks < 4; ks++) {
                        const uint64_t o = ks * 2;
                        mma_f16_ss(tmem + TM_S1, dq1h + o, dkh2 + o, idescS, ks > 0 ? 1u : 0u);
                        mma_f16_ss(tmem + TM_S1, dq1h + o, dkl + o, idescS, 1u);
                        mma_f16_ss(tmem + TM_S1, dq1l + o, dkh2 + o, idescS, 1u);
                    }
                }
                TC_COMMIT(smb + ATT_MBS);
                (void)dkh;
            }
        }
        mbar_wait(smb + ATT_MBS, (uint32_t)(kt & 1));
        TC_FENCE_AFTER();

        // prefetch K/V(kt+1): S(kt) done => O(kt-1) done (in-order) => stage free
        if (kt + 1 < nkt) {
            fill_kv(kt + 1);
            CP_COMMIT();
        }

        // softmax + STTM P into S region (per-warp disjoint columns)
#pragma unroll
        for (int tsel = 0; tsel < 2; tsel++) {
            if (tsel == 1 && !act1) break;
            const uint32_t tms = (tsel == 0) ? (tmem + TM_S2) : (tmem + TM_S1);
            const bool diag = (kt == ((tsel == 0) ? qhi : qlo));
            float lsum = 0.f;
            uint32_t hibuf[2][16], lobuf[2][16];
#pragma unroll
            for (int half = 0; half < 2; half++) {
                uint32_t sv[32];
                LDTM_X32(sv, tms + cbase + half * 32);
                TC_WAIT_LD();
                const int keyblk = cbase + half * 32;
#pragma unroll
                for (int u = 0; u < 16; u++) {
                    const int c0 = u * 2;
                    float p0 = 0.f, p1 = 0.f;
                    if (!diag || (keyblk + c0 <= r))
                        p0 = __expf(__uint_as_float(sv[c0]) * 0.125f);
                    if (!diag || (keyblk + c0 + 1 <= r))
                        p1 = __expf(__uint_as_float(sv[c0 + 1]) * 0.125f);
                    lsum += p0 + p1;
                    __nv_bfloat16 h0 = __float2bfloat16(p0);
                    __nv_bfloat16 h1 = __float2bfloat16(p1);
                    hibuf[half][u] = pack_bf2(h0, h1);
                    lobuf[half][u] = pack_bf2(__float2bfloat16(p0 - __bfloat162float(h0)),
                                              __float2bfloat16(p1 - __bfloat162float(h1)));
                }
            }
#pragma unroll
            for (int half = 0; half < 2; half++) {
                const uint32_t hcol2 = (uint32_t)(cbase + half * 16);
                STTM_X16(tms + hcol2 + warpofs, hibuf[half]);
                STTM_X16(tms + 32 + hcol2 + warpofs, lobuf[half]);
            }
            if (tsel == 0) lacc2 += lsum; else lacc1 += lsum;
        }
        TC_WAIT_ST();
        TC_FENCE_BEFORE();
        __syncthreads();

        // O MMAs (TS)
        if (wid == 0) {
            TC_FENCE_AFTER();
            if (elect_one()) {
                const uint64_t dvh = make_desc(smb + VH);
                const uint64_t dvl = make_desc(smb + VL);
#pragma unroll
                for (int ks = 0; ks < 8; ks++) {
                    const uint64_t bo = (ks < 4) ? (uint64_t)(ks * 2) : (uint64_t)(512 + (ks - 4) * 2);
                    const uint32_t aoh = (uint32_t)(((ks >> 2) * 64) + (ks & 3) * 8);
                    const uint32_t ph2 = tmem + TM_S2 + aoh;
                    const uint32_t pl2 = tmem + TM_S2 + 32 + aoh;
                    mma_f16_ts(tmem + TM_O2, ph2, dvh + bo, idescO, (kt > 0 || ks > 0) ? 1u : 0u);
                    mma_f16_ts(tmem + TM_O2, ph2, dvl + bo, idescO, 1u);
                    mma_f16_ts(tmem + TM_O2, pl2, dvh + bo, idescO, 1u);
                }
                if (act1) {
#pragma unroll
                    for (int ks = 0; ks < 8; ks++) {
                        const uint64_t bo = (ks < 4) ? (uint64_t)(ks * 2) : (uint64_t)(512 + (ks - 4) * 2);
                        const uint32_t aoh = (uint32_t)(((ks >> 2) * 64) + (ks & 3) * 8);
                        const uint32_t ph1 = tmem + TM_S1 + aoh;
                        const uint32_t pl1 = tmem + TM_S1 + 32 + aoh;
                        mma_f16_ts(tmem + TM_O1, ph1, dvh + bo, idescO, (kt > 0 || ks > 0) ? 1u : 0u);
                        mma_f16_ts(tmem + TM_O1, ph1, dvl + bo, idescO, 1u);
                        mma_f16_ts(tmem + TM_O1, pl1, dvh + bo, idescO, 1u);
                    }
                }
                TC_COMMIT(mbo);
            }
        }
    }

    {
        const uint32_t mbf = smb + (((nkt - 1) & 1) ? ATT_MBO1 : ATT_MBO0);
        mbar_wait(mbf, (uint32_t)(((nkt - 1) >> 1) & 1));
    }
    TC_FENCE_AFTER();

    float* ls = (float*)(smem + AQ1H);
    ls[(wid >> 2) * 128 + r] = lacc1;
    ls[256 + (wid >> 2) * 128 + r] = lacc2;
    __syncthreads();
    const float inv1 = 1.f / (ls[r] + ls[128 + r]);
    const float inv2 = 1.f / (ls[256 + r] + ls[384 + r]);

#pragma unroll
    for (int tsel = 0; tsel < 2; tsel++) {
        const uint32_t tmo = (tsel == 0) ? (tmem + TM_O2) : (tmem + TM_O1);
        const float inv = (tsel == 0) ? inv2 : inv1;
        const int qt = (tsel == 0) ? qhi : qlo;
        uint32_t ov[32];
        LDTM_X32(ov, tmo + (wid >> 2) * 32);
        TC_WAIT_LD();
        uint32_t hb[16], lb[16];
#pragma unroll
        for (int u = 0; u < 16; u++) {
            const float v0 = __uint_as_float(ov[2 * u]) * inv;
            const float v1 = __uint_as_float(ov[2 * u + 1]) * inv;
            __nv_bfloat16 h0 = __float2bfloat16(v0), h1 = __float2bfloat16(v1);
            hb[u] = pack_bf2(h0, h1);
            lb[u] = pack_bf2(__float2bfloat16(v0 - __bfloat162float(h0)),
                             __float2bfloat16(v1 - __bfloat162float(h1)));
        }
        const size_t o = ((size_t)b * SEQ + qt * 128 + r) * DMODEL + h * 64 + (wid >> 2) * 32;
#pragma unroll
        for (int u = 0; u < 4; u++) {
            *(uint4*)(g_AOhi + o + u * 8) = *(uint4*)&hb[u * 4];
            *(uint4*)(g_AOlo + o + u * 8) = *(uint4*)&lb[u * 4];
        }
    }
    TC_FENCE_BEFORE();
    __syncthreads();
    if (tid == 0) {
        MBAR_INVAL(smb + ATT_MBS);
        MBAR_INVAL(smb + ATT_MBO0);
        MBAR_INVAL(smb + ATT_MBO1);
    }
    if (wid == 0) TC_DEALLOC(tmem, 512);
#else
    // fallback (never selected at runtime)
    const int tid = threadIdx.x;
    if (tid < 128) {
        for (int tsel = 0; tsel < 2; tsel++) {
            const int qt = (tsel == 0) ? qhi : qlo;
            const int rq = qt * 128 + tid;
            const __nv_bfloat16* qh = Qh + (((size_t)b * NHEAD + h) * SEQ + rq) * HD;
            const __nv_bfloat16* ql = Ql + (((size_t)b * NHEAD + h) * SEQ + rq) * HD;
            float q[HD];
            for (int d = 0; d < HD; d++)
                q[d] = __bfloat162float(qh[d]) + __bfloat162float(ql[d]);
            float l = 0.f, o[HD];
            for (int d = 0; d < HD; d++) o[d] = 0.f;
            for (int s = 0; s <= rq; s++) {
                const __nv_bfloat16* kh = Kh + (((size_t)b * NKV + g) * SEQ + s) * HD;
                const __nv_bfloat16* kl = Kl + (((size_t)b * NKV + g) * SEQ + s) * HD;
                float sc = 0.f;
                for (int d = 0; d < HD; d++)
                    sc += q[d] * (__bfloat162float(kh[d]) + __bfloat162float(kl[d]));
                float pp = __expf(sc * 0.125f);
                l += pp;
                for (int d = 0; d < HD; d++) {
                    const size_t vo = (((size_t)b * NKV + g) * HD + d) * SEQ + s;
                    o[d] += pp * (__bfloat162float(Vth[vo]) + __bfloat162float(Vtl[vo]));
                }
            }
            for (int d = 0; d < HD; d++) {
                const float vv = o[d] / l;
                __nv_bfloat16 hh = __float2bfloat16(vv);
                const size_t oo = ((size_t)b * SEQ + rq) * DMODEL + h * 64 + d;
                g_AOhi[oo] = hh;
                g_AOlo[oo] = __float2bfloat16(vv - __bfloat162float(hh));
            }
        }
    }
#endif
}

// ---------------- launch -----------------------------------------------------------
extern "C" void kernel_launch(void* const* d_in, const int* in_sizes, int n_in,
                              void* d_out, int out_size)
{
    const float* x   = (const float*)d_in[0];
    const int*   pos = (const int*)  d_in[1];
    const float* q_w = (const float*)d_in[2];
    const float* q_b = (const float*)d_in[3];
    const float* k_w = (const float*)d_in[4];
    const float* k_b = (const float*)d_in[5];
    const float* v_w = (const float*)d_in[6];
    const float* v_b = (const float*)d_in[7];
    const float* o_w = (const float*)d_in[8];
    const float* o_b = (const float*)d_in[9];
    float* out = (float*)d_out;

    float* Vp;
    __nv_bfloat16 *Whi, *Wlo, *Xhi, *Xlo, *AOhi, *AOlo;
    __nv_bfloat16 *Qhb, *Qlb, *Khb, *Klb, *Vthb, *Vtlb;
    cudaGetSymbolAddress((void**)&Vp, g_Vp);
    cudaGetSymbolAddress((void**)&Whi, g_Whi);
    cudaGetSymbolAddress((void**)&Wlo, g_Wlo);
    cudaGetSymbolAddress((void**)&Xhi, g_Xhi);
    cudaGetSymbolAddress((void**)&Xlo, g_Xlo);
    cudaGetSymbolAddress((void**)&AOhi, g_AOhi);
    cudaGetSymbolAddress((void**)&AOlo, g_AOlo);
    cudaGetSymbolAddress((void**)&Qhb, g_Qhb);
    cudaGetSymbolAddress((void**)&Qlb, g_Qlb);
    cudaGetSymbolAddress((void**)&Khb, g_Khb);
    cudaGetSymbolAddress((void**)&Klb, g_Klb);
    cudaGetSymbolAddress((void**)&Vthb, g_Vthb);
    cudaGetSymbolAddress((void**)&Vtlb, g_Vtlb);

    cudaFuncSetAttribute(gemm_tc_kernel,
                         cudaFuncAttributeMaxDynamicSharedMemorySize, GSM_TOTAL);
    cudaFuncSetAttribute(attn_tc_kernel,
                         cudaFuncAttributeMaxDynamicSharedMemorySize, ATT_TOTAL);

    wsplit_all_kernel<<<dim3(24, 64), dim3(32, 8)>>>(q_w, k_w, v_w, o_w);
    asplit_kernel<<<(MROWS * KDIM / 4) / 256, 256>>>(x, Xhi, Xlo);
    ropetab_kernel<<<SEQ, 32>>>(pos);
    gemm_tc_kernel<<<dim3(NQKV / 128, MROWS / 128), 256, GSM_TOTAL>>>(
        Xhi, Xlo, Whi + WQ_OFF, Wlo + WQ_OFF, q_b, k_b, v_b, Vp, NQKV, 1);
    vtsplit_kernel<<<dim3(SEQ / 32, HD / 32, BATCH * NKV), dim3(32, 8)>>>(Vp, Vthb, Vtlb);
    attn_tc_kernel<<<dim3(SEQ / 256, NHEAD, BATCH), 256, ATT_TOTAL>>>(
        Qhb, Qlb, Khb, Klb, Vthb, Vtlb);
    gemm_tc_kernel<<<dim3(768 / 128, MROWS / 128), 256, GSM_TOTAL>>>(
        AOhi, AOlo, Whi + WO_OFF, Wlo + WO_OFF, o_b, o_b, o_b, out, 768, 0);
}